// round 8
// baseline (speedup 1.0000x reference)
#include <cuda_runtime.h>
#include <cuda_bf16.h>

#define B_ 4
#define H_ 16
#define NQ 256
#define D_ 16

typedef unsigned long long u64;

#define ABSM 0x7FFFFFFF7FFFFFFFULL

// ---- packed f32x2 helpers (sm_100a) ---------------------------------------
__device__ __forceinline__ u64 pk(float a, float b) {
    u64 r; asm("mov.b64 %0, {%1,%2};" : "=l"(r) : "f"(a), "f"(b)); return r;
}
__device__ __forceinline__ void upk(u64 v, float& a, float& b) {
    asm("mov.b64 {%0,%1}, %2;" : "=f"(a), "=f"(b) : "l"(v));
}
__device__ __forceinline__ u64 fma2_(u64 a, u64 b, u64 c) {
    u64 r; asm("fma.rn.f32x2 %0, %1, %2, %3;" : "=l"(r) : "l"(a), "l"(b), "l"(c));
    return r;
}
__device__ __forceinline__ u64 add2_(u64 a, u64 b) {
    u64 r; asm("add.rn.f32x2 %0, %1, %2;" : "=l"(r) : "l"(a), "l"(b));
    return r;
}
__device__ __forceinline__ u64 mul2_(u64 a, u64 b) {
    u64 r; asm("mul.rn.f32x2 %0, %1, %2;" : "=l"(r) : "l"(a), "l"(b));
    return r;
}

// Scratch for projected Q/K/V in [b][h][n][d] layout.
__device__ float g_Q[B_ * H_ * NQ * D_];
__device__ float g_K[B_ * H_ * NQ * D_];
__device__ float g_V[B_ * H_ * NQ * D_];

// ---------------------------------------------------------------------------
// Kernel A: QKV projections.  out[m, hd] = sum_e A[m, e] * W[hd, e]
// 512 threads/block (16 warps -> real latency hiding), tile 64x64,
// 2x4 micro-tile, K-step 16, double-buffered smem, packed-f32x2 inner.
// Staging split: threads 0-255 load A, 256-511 load W (1 float4 each / step).
// ---------------------------------------------------------------------------
__global__ __launch_bounds__(512) void qkv_kernel(
    const float* __restrict__ row_emb, const float* __restrict__ col_emb,
    const float* __restrict__ Wq, const float* __restrict__ Wk,
    const float* __restrict__ Wv)
{
    __shared__ float As[2][16][68];   // [stage][k][m], padded
    __shared__ float Ws[2][16][68];   // [stage][k][n], padded

    const float* A; const float* W; float* O;
    int z = blockIdx.z;
    if (z == 0)      { A = row_emb; W = Wq; O = g_Q; }
    else if (z == 1) { A = col_emb; W = Wk; O = g_K; }
    else             { A = col_emb; W = Wv; O = g_V; }

    int m0 = blockIdx.y * 64;
    int n0 = blockIdx.x * 64;
    int t  = threadIdx.x;
    int tx = t & 15;          // n-subtile: cols tx*4 .. tx*4+3
    int ty = t >> 4;          // 0..31: rows ty*2, ty*2+1

    bool loadA = t < 256;
    int u  = loadA ? t : t - 256;
    int lm = u >> 2, lk = (u & 3) * 4;
    const float* Sp = loadA ? &A[(m0 + lm) * 256 + lk]
                            : &W[(n0 + lm) * 256 + lk];

    u64 acc[2][2];
    acc[0][0] = acc[0][1] = acc[1][0] = acc[1][1] = 0ull;

    // Prologue: fill stage 0.
    {
        float4 v = *(const float4*)Sp;
        float (*S)[68] = loadA ? As[0] : Ws[0];
        S[lk + 0][lm] = v.x; S[lk + 1][lm] = v.y;
        S[lk + 2][lm] = v.z; S[lk + 3][lm] = v.w;
    }
    __syncthreads();

    for (int k0 = 0; k0 < 256; k0 += 16) {
        int cur = (k0 >> 4) & 1, nxt = cur ^ 1;
        float4 v;
        bool more = (k0 + 16) < 256;
        if (more) v = *(const float4*)(Sp + k0 + 16);
        #pragma unroll
        for (int k = 0; k < 16; k++) {
            float2 a2 = *(const float2*)&As[cur][k][ty * 2];
            float4 b4 = *(const float4*)&Ws[cur][k][tx * 4];
            u64 b01 = pk(b4.x, b4.y);
            u64 b23 = pk(b4.z, b4.w);
            u64 a0  = pk(a2.x, a2.x);
            u64 a1  = pk(a2.y, a2.y);
            acc[0][0] = fma2_(a0, b01, acc[0][0]);
            acc[0][1] = fma2_(a0, b23, acc[0][1]);
            acc[1][0] = fma2_(a1, b01, acc[1][0]);
            acc[1][1] = fma2_(a1, b23, acc[1][1]);
        }
        if (more) {
            float (*S)[68] = loadA ? As[nxt] : Ws[nxt];
            S[lk + 0][lm] = v.x; S[lk + 1][lm] = v.y;
            S[lk + 2][lm] = v.z; S[lk + 3][lm] = v.w;
            __syncthreads();
        }
    }

    int bb = m0 >> 8;
    int hh = (n0 >> 4) + (tx >> 2);
    int dd = (tx & 3) * 4;
    #pragma unroll
    for (int i = 0; i < 2; i++) {
        int r = (m0 + ty * 2 + i) & 255;
        float4 o;
        upk(acc[i][0], o.x, o.y);
        upk(acc[i][1], o.z, o.w);
        *(float4*)&O[((bb * H_ + hh) * NQ + r) * D_ + dd] = o;
    }
}

// ---------------------------------------------------------------------------
// Reduce-scatter over 32 lanes: input acc[8] packed u64 = 16 floats (d pairs).
// Returns full 32-lane sum for d = f(lane); every xor-1 lane pair agrees.
// ---------------------------------------------------------------------------
__device__ __forceinline__ float reduce16(const u64 acc[8], int lane, int& dOut)
{
    bool k16 = (lane & 16) == 0;
    u64 h[4];
    #pragma unroll
    for (int j = 0; j < 4; j++) {
        u64 send = k16 ? acc[4 + j] : acc[j];
        u64 recv = __shfl_xor_sync(0xffffffffu, send, 16);
        u64 mine = k16 ? acc[j] : acc[4 + j];
        h[j] = add2_(mine, recv);
    }
    bool k8 = (lane & 8) == 0;
    u64 g[2];
    #pragma unroll
    for (int j = 0; j < 2; j++) {
        u64 send = k8 ? h[2 + j] : h[j];
        u64 recv = __shfl_xor_sync(0xffffffffu, send, 8);
        u64 mine = k8 ? h[j] : h[2 + j];
        g[j] = add2_(mine, recv);
    }
    bool k4 = (lane & 4) == 0;
    {
        u64 send = k4 ? g[1] : g[0];
        u64 recv = __shfl_xor_sync(0xffffffffu, send, 4);
        u64 mine = k4 ? g[0] : g[1];
        g[0] = add2_(mine, recv);
    }
    float lo, hi; upk(g[0], lo, hi);
    bool k2 = (lane & 2) == 0;
    float send = k2 ? hi : lo;
    float recv = __shfl_xor_sync(0xffffffffu, send, 2);
    float s = (k2 ? lo : hi) + recv;
    s += __shfl_xor_sync(0xffffffffu, s, 1);
    dOut = ((lane & 16) >> 1) | ((lane & 8) >> 1) | ((lane & 4) >> 1) | ((lane & 2) >> 1);
    return s;
}

// ---------------------------------------------------------------------------
// Kernel B: fused scores + mixing-MLP + softmax + AV.
// One warp per TWO rows, fully row-pair packed: phase 1 is 128 fma2/warp
// using K duplicated in smem as (k,k) u64 pairs (conflict-free stride 18),
// q packed as (q0,q1).  dp/cp/score pairs all hold (row0,row1).
// Kdup buffer is reused for the V tile after phase 1 (sync-guarded).
// MLP identity: sum w2*relu(t) = A*dot + B*cost + [C] + sum (0.5w2)|t|,
// C and mix2_bias softmax-invariant (dropped); 1/sqrt(D) folded into w1a.
// ---------------------------------------------------------------------------
__global__ __launch_bounds__(256, 3) void attn_kernel(
    const float* __restrict__ cost_mat,
    const float* __restrict__ mix1_w,   // [16][2][32]
    const float* __restrict__ mix1_b,   // [16][32]
    const float* __restrict__ mix2_w,   // [16][32][1]
    float* __restrict__ out)            // [B][R][H*D]
{
    __shared__ __align__(16) char smem_raw[256 * 18 * 8];   // 36 KB union
    __shared__ u64 mlpp[32][4];        // (wx pair, wy pair, b1 pair, 0.5*w2 pair)
    __shared__ u64 ABs[2];             // packed (A,A), (B,B)

    u64   (*Kdup)[18] = reinterpret_cast<u64(*)[18]>(smem_raw);   // phase 1
    float (*Vs)[20]   = reinterpret_cast<float(*)[20]>(smem_raw); // phase 4

    int b = blockIdx.z, h = blockIdx.y, rt = blockIdx.x;
    int bh = b * H_ + h;
    int t = threadIdx.x;
    int lane = t & 31, w = t >> 5;
    int r0 = rt * 16 + w * 2;           // this warp handles rows r0, r0+1

    // ---- stage K duplicated: Kdup[c][d] = (K[c][d], K[c][d]) ----
    {
        const float* Kg = g_K + (bh * NQ + t) * D_;
        #pragma unroll
        for (int j = 0; j < 4; j++) {
            float4 k4 = *(const float4*)&Kg[j * 4];
            Kdup[t][j * 4 + 0] = pk(k4.x, k4.x);
            Kdup[t][j * 4 + 1] = pk(k4.y, k4.y);
            Kdup[t][j * 4 + 2] = pk(k4.z, k4.z);
            Kdup[t][j * 4 + 3] = pk(k4.w, k4.w);
        }
    }
    if (t < 32) {
        float wxv = mix1_w[h * 64 + t] * 0.25f;   // fold 1/sqrt(D)
        float wyv = mix1_w[h * 64 + 32 + t];
        float bzv = mix1_b[h * 32 + t];
        float hwv = mix2_w[h * 32 + t] * 0.5f;    // fold 0.5 of abs-relu identity
        mlpp[t][0] = pk(wxv, wxv);
        mlpp[t][1] = pk(wyv, wyv);
        mlpp[t][2] = pk(bzv, bzv);
        mlpp[t][3] = pk(hwv, hwv);
        float a  = hwv * wxv;
        float bb = hwv * wyv;
        #pragma unroll
        for (int o = 16; o; o >>= 1) {
            a  += __shfl_xor_sync(0xffffffffu, a, o);
            bb += __shfl_xor_sync(0xffffffffu, bb, o);
        }
        if (t == 0) { ABs[0] = pk(a, a); ABs[1] = pk(bb, bb); }
    }
    __syncthreads();

    // ---- Phase 1: packed dot scores, dp[i] = (dot_r0, dot_r1) for col i ----
    u64 qp[16];
    {
        const float* Qg = g_Q + (bh * NQ + r0) * D_;
        #pragma unroll
        for (int j = 0; j < 4; j++) {
            float4 a = *(const float4*)&Qg[j * 4];
            float4 c = *(const float4*)&Qg[16 + j * 4];
            qp[j * 4 + 0] = pk(a.x, c.x);
            qp[j * 4 + 1] = pk(a.y, c.y);
            qp[j * 4 + 2] = pk(a.z, c.z);
            qp[j * 4 + 3] = pk(a.w, c.w);
        }
    }
    u64 dp[8];
    #pragma unroll
    for (int i = 0; i < 8; i++) {
        int c = i * 32 + lane;
        u64 s = 0ull;
        #pragma unroll
        for (int j = 0; j < 8; j++) {
            ulonglong2 kk = *(const ulonglong2*)&Kdup[c][2 * j];
            s = fma2_(qp[2 * j],     kk.x, s);
            s = fma2_(qp[2 * j + 1], kk.y, s);
        }
        dp[i] = s;
    }
    __syncthreads();   // all warps done reading Kdup

    // ---- stage V into the same buffer; cost loads overlap ----
    float4 v4[4];
    {
        const float* Vg = g_V + (bh * NQ + t) * D_;
        #pragma unroll
        for (int j = 0; j < 4; j++) v4[j] = *(const float4*)&Vg[j * 4];
    }
    const float* cr0 = cost_mat + (b * NQ + r0) * NQ;
    const float* cr1 = cr0 + NQ;
    u64 cp[8];
    #pragma unroll
    for (int i = 0; i < 8; i++) {
        int c = i * 32 + lane;
        cp[i] = pk(__ldg(cr0 + c), __ldg(cr1 + c));
    }
    #pragma unroll
    for (int j = 0; j < 4; j++) *(float4*)&Vs[t][j * 4] = v4[j];
    __syncthreads();

    // ---- Phase 2: mixing MLP (abs half only; linear half analytic) ----
    u64 A2 = ABs[0], B2 = ABs[1];
    u64 s[8];
    #pragma unroll
    for (int i = 0; i < 8; i++)
        s[i] = fma2_(B2, cp[i], mul2_(A2, dp[i]));
    #pragma unroll 4
    for (int m = 0; m < 32; m++) {
        ulonglong2 w01 = *(const ulonglong2*)&mlpp[m][0];
        ulonglong2 w23 = *(const ulonglong2*)&mlpp[m][2];
        #pragma unroll
        for (int i = 0; i < 8; i++) {
            u64 t0 = fma2_(w01.x, dp[i], fma2_(w01.y, cp[i], w23.x));
            s[i] = fma2_(w23.y, t0 & ABSM, s[i]);
        }
    }

    // ---- Phase 3: softmax per row (pairs are (row0,row1)) ----
    float sc0[8], sc1[8];
    #pragma unroll
    for (int i = 0; i < 8; i++) upk(s[i], sc0[i], sc1[i]);
    float mx0 = sc0[0], mx1 = sc1[0];
    #pragma unroll
    for (int i = 1; i < 8; i++) { mx0 = fmaxf(mx0, sc0[i]); mx1 = fmaxf(mx1, sc1[i]); }
    #pragma unroll
    for (int o = 16; o; o >>= 1) {
        mx0 = fmaxf(mx0, __shfl_xor_sync(0xffffffffu, mx0, o));
        mx1 = fmaxf(mx1, __shfl_xor_sync(0xffffffffu, mx1, o));
    }
    float sum0 = 0.f, sum1 = 0.f;
    #pragma unroll
    for (int i = 0; i < 8; i++) {
        sc0[i] = __expf(sc0[i] - mx0); sum0 += sc0[i];
        sc1[i] = __expf(sc1[i] - mx1); sum1 += sc1[i];
    }
    #pragma unroll
    for (int o = 16; o; o >>= 1) {
        sum0 += __shfl_xor_sync(0xffffffffu, sum0, o);
        sum1 += __shfl_xor_sync(0xffffffffu, sum1, o);
    }
    float inv0 = 1.f / sum0, inv1 = 1.f / sum1;

    // ---- Phase 4: AV accumulation (packed over d pairs) ----
    u64 acc0[8], acc1[8];
    #pragma unroll
    for (int j = 0; j < 8; j++) { acc0[j] = 0ull; acc1[j] = 0ull; }
    #pragma unroll
    for (int i = 0; i < 8; i++) {
        int c = i * 32 + lane;
        u64 w0 = pk(sc0[i], sc0[i]);
        u64 w1 = pk(sc1[i], sc1[i]);
        #pragma unroll
        for (int j = 0; j < 4; j++) {
            float4 vv = *(const float4*)&Vs[c][j * 4];
            u64 vA = pk(vv.x, vv.y);
            u64 vB = pk(vv.z, vv.w);
            acc0[2 * j]     = fma2_(w0, vA, acc0[2 * j]);
            acc0[2 * j + 1] = fma2_(w0, vB, acc0[2 * j + 1]);
            acc1[2 * j]     = fma2_(w1, vA, acc1[2 * j]);
            acc1[2 * j + 1] = fma2_(w1, vB, acc1[2 * j + 1]);
        }
    }

    // ---- Phase 5: reduce-scatter epilogue ----
    int d0;
    float res0 = reduce16(acc0, lane, d0);
    int d1;
    float res1 = reduce16(acc1, lane, d1);
    if ((lane & 1) == 0) {
        out[(b * NQ + r0)     * (H_ * D_) + h * D_ + d0] = res0 * inv0;
        out[(b * NQ + r0 + 1) * (H_ * D_) + h * D_ + d1] = res1 * inv1;
    }
}

extern "C" void kernel_launch(void* const* d_in, const int* in_sizes, int n_in,
                              void* d_out, int out_size)
{
    const float* row_emb  = (const float*)d_in[0];
    const float* col_emb  = (const float*)d_in[1];
    const float* cost_mat = (const float*)d_in[2];
    const float* Wq       = (const float*)d_in[3];
    const float* Wk       = (const float*)d_in[4];
    const float* Wv       = (const float*)d_in[5];
    const float* m1w      = (const float*)d_in[6];
    const float* m1b      = (const float*)d_in[7];
    const float* m2w      = (const float*)d_in[8];
    // d_in[9] = mix2_bias: softmax-invariant, intentionally unused.
    float* out = (float*)d_out;

    dim3 gA(4, 16, 3);   // n-tiles x m-tiles x {Q,K,V}
    qkv_kernel<<<gA, 512>>>(row_emb, col_emb, Wq, Wk, Wv);

    dim3 gB(16, 16, 4);  // 16-row tiles x heads x batch
    attn_kernel<<<gB, 256>>>(cost_mat, m1w, m1b, m2w, out);
}

// round 9
// speedup vs baseline: 1.1697x; 1.1697x over previous
#include <cuda_runtime.h>
#include <cuda_bf16.h>

#define B_ 4
#define H_ 16
#define NQ 256
#define D_ 16

typedef unsigned long long u64;

#define ABSM 0x7FFFFFFF7FFFFFFFULL

// ---- packed f32x2 helpers (sm_100a) ---------------------------------------
__device__ __forceinline__ u64 pk(float a, float b) {
    u64 r; asm("mov.b64 %0, {%1,%2};" : "=l"(r) : "f"(a), "f"(b)); return r;
}
__device__ __forceinline__ void upk(u64 v, float& a, float& b) {
    asm("mov.b64 {%0,%1}, %2;" : "=f"(a), "=f"(b) : "l"(v));
}
__device__ __forceinline__ u64 fma2_(u64 a, u64 b, u64 c) {
    u64 r; asm("fma.rn.f32x2 %0, %1, %2, %3;" : "=l"(r) : "l"(a), "l"(b), "l"(c));
    return r;
}
__device__ __forceinline__ u64 add2_(u64 a, u64 b) {
    u64 r; asm("add.rn.f32x2 %0, %1, %2;" : "=l"(r) : "l"(a), "l"(b));
    return r;
}
__device__ __forceinline__ u64 mul2_(u64 a, u64 b) {
    u64 r; asm("mul.rn.f32x2 %0, %1, %2;" : "=l"(r) : "l"(a), "l"(b));
    return r;
}

// Scratch for projected Q/K/V in [b][h][n][d] layout.
__device__ float g_Q[B_ * H_ * NQ * D_];
__device__ float g_K[B_ * H_ * NQ * D_];
__device__ float g_V[B_ * H_ * NQ * D_];

// ---------------------------------------------------------------------------
// Kernel A: QKV projections.  out[m, hd] = sum_e A[m, e] * W[hd, e]
// Tiled 64x64, 256 threads, 4x4 micro-tile, K-step 16, double-buffered smem,
// packed-f32x2 inner.  B-operand pairs come straight from aligned LDS.128
// (ulonglong2 view of the padded row: 68 floats = 272B = 16B multiple).
// ---------------------------------------------------------------------------
__global__ __launch_bounds__(256) void qkv_kernel(
    const float* __restrict__ row_emb, const float* __restrict__ col_emb,
    const float* __restrict__ Wq, const float* __restrict__ Wk,
    const float* __restrict__ Wv)
{
    __shared__ __align__(16) float As[2][16][68];   // [stage][k][m], padded
    __shared__ __align__(16) float Ws[2][16][68];   // [stage][k][n], padded

    const float* A; const float* W; float* O;
    int z = blockIdx.z;
    if (z == 0)      { A = row_emb; W = Wq; O = g_Q; }
    else if (z == 1) { A = col_emb; W = Wk; O = g_K; }
    else             { A = col_emb; W = Wv; O = g_V; }

    int m0 = blockIdx.y * 64;
    int n0 = blockIdx.x * 64;
    int t  = threadIdx.x;
    int tx = t & 15, ty = t >> 4;
    int lm = t >> 2, lk = (t & 3) * 4;

    const float* Ap = &A[(m0 + lm) * 256 + lk];
    const float* Wp = &W[(n0 + lm) * 256 + lk];

    u64 accp[4][2];
    #pragma unroll
    for (int i = 0; i < 4; i++) { accp[i][0] = 0ull; accp[i][1] = 0ull; }

    // Prologue: fill stage 0.
    {
        float4 av = *(const float4*)Ap;
        float4 wv = *(const float4*)Wp;
        As[0][lk + 0][lm] = av.x; As[0][lk + 1][lm] = av.y;
        As[0][lk + 2][lm] = av.z; As[0][lk + 3][lm] = av.w;
        Ws[0][lk + 0][lm] = wv.x; Ws[0][lk + 1][lm] = wv.y;
        Ws[0][lk + 2][lm] = wv.z; Ws[0][lk + 3][lm] = wv.w;
    }
    __syncthreads();

    for (int k0 = 0; k0 < 256; k0 += 16) {
        int cur = (k0 >> 4) & 1, nxt = cur ^ 1;
        float4 av, wv;
        bool more = (k0 + 16) < 256;
        if (more) {
            av = *(const float4*)(Ap + k0 + 16);
            wv = *(const float4*)(Wp + k0 + 16);
        }
        #pragma unroll
        for (int k = 0; k < 16; k++) {
            float4 a = *(const float4*)&As[cur][k][ty * 4];
            ulonglong2 bb = *(const ulonglong2*)&Ws[cur][k][tx * 4];  // (b0,b1),(b2,b3) free pairs
            float am[4] = {a.x, a.y, a.z, a.w};
            #pragma unroll
            for (int i = 0; i < 4; i++) {
                u64 aa = pk(am[i], am[i]);
                accp[i][0] = fma2_(aa, bb.x, accp[i][0]);
                accp[i][1] = fma2_(aa, bb.y, accp[i][1]);
            }
        }
        if (more) {
            As[nxt][lk + 0][lm] = av.x; As[nxt][lk + 1][lm] = av.y;
            As[nxt][lk + 2][lm] = av.z; As[nxt][lk + 3][lm] = av.w;
            Ws[nxt][lk + 0][lm] = wv.x; Ws[nxt][lk + 1][lm] = wv.y;
            Ws[nxt][lk + 2][lm] = wv.z; Ws[nxt][lk + 3][lm] = wv.w;
            __syncthreads();
        }
    }

    int bb = m0 >> 8;
    int hh = (n0 >> 4) + (tx >> 2);
    int dd = (tx & 3) * 4;
    #pragma unroll
    for (int i = 0; i < 4; i++) {
        int m = m0 + ty * 4 + i;
        int r = m & 255;
        float4 o;
        upk(accp[i][0], o.x, o.y);
        upk(accp[i][1], o.z, o.w);
        *(float4*)&O[((bb * H_ + hh) * NQ + r) * D_ + dd] = o;
    }
}

// ---------------------------------------------------------------------------
// Reduce-scatter over 32 lanes: input acc[8] packed u64 = 16 floats (d pairs).
// Returns full 32-lane sum for d = f(lane); every xor-1 lane pair agrees.
// ---------------------------------------------------------------------------
__device__ __forceinline__ float reduce16(const u64 acc[8], int lane, int& dOut)
{
    bool k16 = (lane & 16) == 0;
    u64 h[4];
    #pragma unroll
    for (int j = 0; j < 4; j++) {
        u64 send = k16 ? acc[4 + j] : acc[j];
        u64 recv = __shfl_xor_sync(0xffffffffu, send, 16);
        u64 mine = k16 ? acc[j] : acc[4 + j];
        h[j] = add2_(mine, recv);
    }
    bool k8 = (lane & 8) == 0;
    u64 g[2];
    #pragma unroll
    for (int j = 0; j < 2; j++) {
        u64 send = k8 ? h[2 + j] : h[j];
        u64 recv = __shfl_xor_sync(0xffffffffu, send, 8);
        u64 mine = k8 ? h[j] : h[2 + j];
        g[j] = add2_(mine, recv);
    }
    bool k4 = (lane & 4) == 0;
    {
        u64 send = k4 ? g[1] : g[0];
        u64 recv = __shfl_xor_sync(0xffffffffu, send, 4);
        u64 mine = k4 ? g[0] : g[1];
        g[0] = add2_(mine, recv);
    }
    float lo, hi; upk(g[0], lo, hi);
    bool k2 = (lane & 2) == 0;
    float send = k2 ? hi : lo;
    float recv = __shfl_xor_sync(0xffffffffu, send, 2);
    float s = (k2 ? lo : hi) + recv;
    s += __shfl_xor_sync(0xffffffffu, s, 1);
    dOut = ((lane & 16) >> 1) | ((lane & 8) >> 1) | ((lane & 4) >> 1) | ((lane & 2) >> 1);
    return s;
}

// ---------------------------------------------------------------------------
// Kernel B: fused scores + mixing-MLP + softmax + AV.
// One warp per TWO rows.  MLP identity:
//   sum_m w2*relu(t_m) = A*dot + B*cost + [C] + sum_m (0.5*w2_m)*|t_m|
// with A = sum 0.5*w2*w1a, B = sum 0.5*w2*w1b; C and mix2_bias are
// softmax-invariant (dropped).  1/sqrt(D) folded into w1a.
// launch_bounds(256,4) caps regs at 64 -> 4 blocks/SM (32 warps resident).
// ---------------------------------------------------------------------------
__global__ __launch_bounds__(256, 4) void attn_kernel(
    const float* __restrict__ cost_mat,
    const float* __restrict__ mix1_w,   // [16][2][32]
    const float* __restrict__ mix1_b,   // [16][32]
    const float* __restrict__ mix2_w,   // [16][32][1]
    float* __restrict__ out)            // [B][R][H*D]
{
    __shared__ __align__(16) float Ks[256][20];
    __shared__ __align__(16) float Vs[256][20];
    __shared__ u64   mlpp[32][4];       // (wx pair, wy pair, b1 pair, 0.5*w2 pair)
    __shared__ u64   ABs[2];            // packed (A,A), (B,B)

    int b = blockIdx.z, h = blockIdx.y, rt = blockIdx.x;
    int bh = b * H_ + h;
    int t = threadIdx.x;
    int lane = t & 31, w = t >> 5;
    int r0 = rt * 16 + w * 2;           // this warp handles rows r0, r0+1

    // ---- cooperative K/V tile staging ----
    {
        const float* Kg = g_K + bh * NQ * D_;
        const float* Vg = g_V + bh * NQ * D_;
        #pragma unroll
        for (int j = 0; j < 4; j++) {
            *(float4*)&Ks[t][j * 4] = *(const float4*)&Kg[t * D_ + j * 4];
            *(float4*)&Vs[t][j * 4] = *(const float4*)&Vg[t * D_ + j * 4];
        }
    }
    if (t < 32) {
        float wxv = mix1_w[h * 64 + t] * 0.25f;   // fold 1/sqrt(D)
        float wyv = mix1_w[h * 64 + 32 + t];
        float bzv = mix1_b[h * 32 + t];
        float hwv = mix2_w[h * 32 + t] * 0.5f;    // fold 0.5 of abs-relu identity
        mlpp[t][0] = pk(wxv, wxv);
        mlpp[t][1] = pk(wyv, wyv);
        mlpp[t][2] = pk(bzv, bzv);
        mlpp[t][3] = pk(hwv, hwv);
        float a  = hwv * wxv;
        float bb = hwv * wyv;
        #pragma unroll
        for (int o = 16; o; o >>= 1) {
            a  += __shfl_xor_sync(0xffffffffu, a, o);
            bb += __shfl_xor_sync(0xffffffffu, bb, o);
        }
        if (t == 0) { ABs[0] = pk(a, a); ABs[1] = pk(bb, bb); }
    }
    __syncthreads();

    // ---- Phase 1: raw dot scores (scale folded into wx) ----
    float q0[16], q1[16];
    {
        const float* Qg = g_Q + (bh * NQ + r0) * D_;
        #pragma unroll
        for (int j = 0; j < 4; j++) {
            float4 a = *(const float4*)&Qg[j * 4];
            float4 c = *(const float4*)&Qg[16 + j * 4];
            q0[j*4+0] = a.x; q0[j*4+1] = a.y; q0[j*4+2] = a.z; q0[j*4+3] = a.w;
            q1[j*4+0] = c.x; q1[j*4+1] = c.y; q1[j*4+2] = c.z; q1[j*4+3] = c.w;
        }
    }
    u64 dp0[4], dp1[4];
    #pragma unroll
    for (int p = 0; p < 4; p++) {
        int ca = (2 * p) * 32 + lane;
        int cb = ca + 32;
        float sa0 = 0.f, sa1 = 0.f, sb0 = 0.f, sb1 = 0.f;
        #pragma unroll
        for (int j = 0; j < 4; j++) {
            float4 ka = *(const float4*)&Ks[ca][j * 4];
            float4 kb = *(const float4*)&Ks[cb][j * 4];
            sa0 = fmaf(q0[j*4+0], ka.x, sa0); sa0 = fmaf(q0[j*4+1], ka.y, sa0);
            sa0 = fmaf(q0[j*4+2], ka.z, sa0); sa0 = fmaf(q0[j*4+3], ka.w, sa0);
            sa1 = fmaf(q1[j*4+0], ka.x, sa1); sa1 = fmaf(q1[j*4+1], ka.y, sa1);
            sa1 = fmaf(q1[j*4+2], ka.z, sa1); sa1 = fmaf(q1[j*4+3], ka.w, sa1);
            sb0 = fmaf(q0[j*4+0], kb.x, sb0); sb0 = fmaf(q0[j*4+1], kb.y, sb0);
            sb0 = fmaf(q0[j*4+2], kb.z, sb0); sb0 = fmaf(q0[j*4+3], kb.w, sb0);
            sb1 = fmaf(q1[j*4+0], kb.x, sb1); sb1 = fmaf(q1[j*4+1], kb.y, sb1);
            sb1 = fmaf(q1[j*4+2], kb.z, sb1); sb1 = fmaf(q1[j*4+3], kb.w, sb1);
        }
        dp0[p] = pk(sa0, sb0);
        dp1[p] = pk(sa1, sb1);
    }

    // ---- cost loads (after phase 1 so q regs can retire first) ----
    const float* cr0 = cost_mat + (b * NQ + r0) * NQ;
    const float* cr1 = cr0 + NQ;
    u64 cp0[4], cp1[4];
    #pragma unroll
    for (int p = 0; p < 4; p++) {
        int ca = (2 * p) * 32 + lane;
        cp0[p] = pk(__ldg(cr0 + ca), __ldg(cr0 + ca + 32));
        cp1[p] = pk(__ldg(cr1 + ca), __ldg(cr1 + ca + 32));
    }

    // ---- Phase 2: mixing MLP (abs half only; linear half analytic) ----
    u64 A2 = ABs[0], B2 = ABs[1];
    u64 s0[4], s1[4];
    #pragma unroll
    for (int p = 0; p < 4; p++) {
        s0[p] = fma2_(B2, cp0[p], mul2_(A2, dp0[p]));
        s1[p] = fma2_(B2, cp1[p], mul2_(A2, dp1[p]));
    }
    #pragma unroll 4
    for (int m = 0; m < 32; m++) {
        ulonglong2 w01 = *(const ulonglong2*)&mlpp[m][0];
        ulonglong2 w23 = *(const ulonglong2*)&mlpp[m][2];
        u64 wxx = w01.x, wyy = w01.y, wzz = w23.x, hww = w23.y;
        #pragma unroll
        for (int p = 0; p < 4; p++) {
            u64 t0 = fma2_(wxx, dp0[p], fma2_(wyy, cp0[p], wzz));
            s0[p] = fma2_(hww, t0 & ABSM, s0[p]);
            u64 t1 = fma2_(wxx, dp1[p], fma2_(wyy, cp1[p], wzz));
            s1[p] = fma2_(hww, t1 & ABSM, s1[p]);
        }
    }

    // ---- Phase 3: softmax per row ----
    float sc0[8], sc1[8];
    #pragma unroll
    for (int p = 0; p < 4; p++) {
        upk(s0[p], sc0[2 * p], sc0[2 * p + 1]);
        upk(s1[p], sc1[2 * p], sc1[2 * p + 1]);
    }
    float mx0 = sc0[0], mx1 = sc1[0];
    #pragma unroll
    for (int i = 1; i < 8; i++) { mx0 = fmaxf(mx0, sc0[i]); mx1 = fmaxf(mx1, sc1[i]); }
    #pragma unroll
    for (int o = 16; o; o >>= 1) {
        mx0 = fmaxf(mx0, __shfl_xor_sync(0xffffffffu, mx0, o));
        mx1 = fmaxf(mx1, __shfl_xor_sync(0xffffffffu, mx1, o));
    }
    float sum0 = 0.f, sum1 = 0.f;
    #pragma unroll
    for (int i = 0; i < 8; i++) {
        sc0[i] = __expf(sc0[i] - mx0); sum0 += sc0[i];
        sc1[i] = __expf(sc1[i] - mx1); sum1 += sc1[i];
    }
    #pragma unroll
    for (int o = 16; o; o >>= 1) {
        sum0 += __shfl_xor_sync(0xffffffffu, sum0, o);
        sum1 += __shfl_xor_sync(0xffffffffu, sum1, o);
    }
    float inv0 = 1.f / sum0, inv1 = 1.f / sum1;

    // ---- Phase 4: AV accumulation (packed over d pairs; V pairs are free
    //      ulonglong2 views of the 16B-aligned smem rows) ----
    u64 acc0[8], acc1[8];
    #pragma unroll
    for (int j = 0; j < 8; j++) { acc0[j] = 0ull; acc1[j] = 0ull; }
    #pragma unroll
    for (int i = 0; i < 8; i++) {
        int c = i * 32 + lane;
        u64 w0 = pk(sc0[i], sc0[i]);
        u64 w1 = pk(sc1[i], sc1[i]);
        #pragma unroll
        for (int j = 0; j < 4; j++) {
            ulonglong2 vv = *(const ulonglong2*)&Vs[c][j * 4];
            acc0[2 * j]     = fma2_(w0, vv.x, acc0[2 * j]);
            acc0[2 * j + 1] = fma2_(w0, vv.y, acc0[2 * j + 1]);
            acc1[2 * j]     = fma2_(w1, vv.x, acc1[2 * j]);
            acc1[2 * j + 1] = fma2_(w1, vv.y, acc1[2 * j + 1]);
        }
    }

    // ---- Phase 5: reduce-scatter epilogue ----
    int d0;
    float res0 = reduce16(acc0, lane, d0);
    int d1;
    float res1 = reduce16(acc1, lane, d1);
    if ((lane & 1) == 0) {
        out[(b * NQ + r0)     * (H_ * D_) + h * D_ + d0] = res0 * inv0;
        out[(b * NQ + r0 + 1) * (H_ * D_) + h * D_ + d1] = res1 * inv1;
    }
}

extern "C" void kernel_launch(void* const* d_in, const int* in_sizes, int n_in,
                              void* d_out, int out_size)
{
    const float* row_emb  = (const float*)d_in[0];
    const float* col_emb  = (const float*)d_in[1];
    const float* cost_mat = (const float*)d_in[2];
    const float* Wq       = (const float*)d_in[3];
    const float* Wk       = (const float*)d_in[4];
    const float* Wv       = (const float*)d_in[5];
    const float* m1w      = (const float*)d_in[6];
    const float* m1b      = (const float*)d_in[7];
    const float* m2w      = (const float*)d_in[8];
    // d_in[9] = mix2_bias: softmax-invariant, intentionally unused.
    float* out = (float*)d_out;

    dim3 gA(4, 16, 3);   // n-tiles x m-tiles x {Q,K,V}
    qkv_kernel<<<gA, 256>>>(row_emb, col_emb, Wq, Wk, Wv);

    dim3 gB(16, 16, 4);  // 16-row tiles x heads x batch
    attn_kernel<<<gB, 256>>>(cost_mat, m1w, m1b, m2w, out);
}

// round 10
// speedup vs baseline: 1.2936x; 1.1059x over previous
#include <cuda_runtime.h>
#include <cuda_bf16.h>

#define B_ 4
#define H_ 16
#define NQ 256
#define D_ 16

typedef unsigned long long u64;

#define ABSM 0x7FFFFFFF7FFFFFFFULL

// ---- packed f32x2 helpers (sm_100a) ---------------------------------------
__device__ __forceinline__ u64 pk(float a, float b) {
    u64 r; asm("mov.b64 %0, {%1,%2};" : "=l"(r) : "f"(a), "f"(b)); return r;
}
__device__ __forceinline__ void upk(u64 v, float& a, float& b) {
    asm("mov.b64 {%0,%1}, %2;" : "=f"(a), "=f"(b) : "l"(v));
}
__device__ __forceinline__ u64 fma2_(u64 a, u64 b, u64 c) {
    u64 r; asm("fma.rn.f32x2 %0, %1, %2, %3;" : "=l"(r) : "l"(a), "l"(b), "l"(c));
    return r;
}
__device__ __forceinline__ u64 add2_(u64 a, u64 b) {
    u64 r; asm("add.rn.f32x2 %0, %1, %2;" : "=l"(r) : "l"(a), "l"(b));
    return r;
}
__device__ __forceinline__ u64 mul2_(u64 a, u64 b) {
    u64 r; asm("mul.rn.f32x2 %0, %1, %2;" : "=l"(r) : "l"(a), "l"(b));
    return r;
}

// Scratch for projected Q/K/V in [b][h][n][d] layout.
__device__ float g_Q[B_ * H_ * NQ * D_];
__device__ float g_K[B_ * H_ * NQ * D_];
__device__ float g_V[B_ * H_ * NQ * D_];

// ---------------------------------------------------------------------------
// Kernel A: QKV projections.  out[m, hd] = sum_e A[m, e] * W[hd, e]
// Tile 32(m) x 64(n), 128 threads, 4x4 micro-tile (16 fma2 : 8 LDS density),
// K-step 16, double-buffered smem.  384 blocks -> 2.6/SM, wave imbalance
// 1.25x (vs 2x at 192 blocks) on this fma-bound kernel.
// ---------------------------------------------------------------------------
__global__ __launch_bounds__(128) void qkv_kernel(
    const float* __restrict__ row_emb, const float* __restrict__ col_emb,
    const float* __restrict__ Wq, const float* __restrict__ Wk,
    const float* __restrict__ Wv)
{
    __shared__ __align__(16) float As[2][16][36];   // [stage][k][m], padded
    __shared__ __align__(16) float Ws[2][16][68];   // [stage][k][n], padded

    const float* A; const float* W; float* O;
    int z = blockIdx.z;
    if (z == 0)      { A = row_emb; W = Wq; O = g_Q; }
    else if (z == 1) { A = col_emb; W = Wk; O = g_K; }
    else             { A = col_emb; W = Wv; O = g_V; }

    int m0 = blockIdx.y * 32;
    int n0 = blockIdx.x * 64;
    int t  = threadIdx.x;
    int tx = t & 15, ty = t >> 4;      // compute map: 16 x 8 threads
    int lm = t >> 2, lk = (t & 3) * 4; // load map: 32 rows x 16 k

    const float* Ap  = &A[(m0 + lm) * 256 + lk];
    const float* Wp0 = &W[(n0 + lm) * 256 + lk];
    const float* Wp1 = &W[(n0 + 32 + lm) * 256 + lk];

    u64 accp[4][2];
    #pragma unroll
    for (int i = 0; i < 4; i++) { accp[i][0] = 0ull; accp[i][1] = 0ull; }

    // Prologue: fill stage 0.
    {
        float4 av = *(const float4*)Ap;
        float4 w0 = *(const float4*)Wp0;
        float4 w1 = *(const float4*)Wp1;
        As[0][lk + 0][lm] = av.x; As[0][lk + 1][lm] = av.y;
        As[0][lk + 2][lm] = av.z; As[0][lk + 3][lm] = av.w;
        Ws[0][lk + 0][lm] = w0.x; Ws[0][lk + 1][lm] = w0.y;
        Ws[0][lk + 2][lm] = w0.z; Ws[0][lk + 3][lm] = w0.w;
        Ws[0][lk + 0][32 + lm] = w1.x; Ws[0][lk + 1][32 + lm] = w1.y;
        Ws[0][lk + 2][32 + lm] = w1.z; Ws[0][lk + 3][32 + lm] = w1.w;
    }
    __syncthreads();

    for (int k0 = 0; k0 < 256; k0 += 16) {
        int cur = (k0 >> 4) & 1, nxt = cur ^ 1;
        float4 av, w0, w1;
        bool more = (k0 + 16) < 256;
        if (more) {
            av = *(const float4*)(Ap  + k0 + 16);
            w0 = *(const float4*)(Wp0 + k0 + 16);
            w1 = *(const float4*)(Wp1 + k0 + 16);
        }
        #pragma unroll
        for (int k = 0; k < 16; k++) {
            float4 a = *(const float4*)&As[cur][k][ty * 4];
            ulonglong2 bb = *(const ulonglong2*)&Ws[cur][k][tx * 4];  // free pairs
            float am[4] = {a.x, a.y, a.z, a.w};
            #pragma unroll
            for (int i = 0; i < 4; i++) {
                u64 aa = pk(am[i], am[i]);
                accp[i][0] = fma2_(aa, bb.x, accp[i][0]);
                accp[i][1] = fma2_(aa, bb.y, accp[i][1]);
            }
        }
        if (more) {
            As[nxt][lk + 0][lm] = av.x; As[nxt][lk + 1][lm] = av.y;
            As[nxt][lk + 2][lm] = av.z; As[nxt][lk + 3][lm] = av.w;
            Ws[nxt][lk + 0][lm] = w0.x; Ws[nxt][lk + 1][lm] = w0.y;
            Ws[nxt][lk + 2][lm] = w0.z; Ws[nxt][lk + 3][lm] = w0.w;
            Ws[nxt][lk + 0][32 + lm] = w1.x; Ws[nxt][lk + 1][32 + lm] = w1.y;
            Ws[nxt][lk + 2][32 + lm] = w1.z; Ws[nxt][lk + 3][32 + lm] = w1.w;
            __syncthreads();
        }
    }

    int bb = m0 >> 8;
    int hh = (n0 >> 4) + (tx >> 2);
    int dd = (tx & 3) * 4;
    #pragma unroll
    for (int i = 0; i < 4; i++) {
        int r = (m0 & 255) + ty * 4 + i;
        float4 o;
        upk(accp[i][0], o.x, o.y);
        upk(accp[i][1], o.z, o.w);
        *(float4*)&O[((bb * H_ + hh) * NQ + r) * D_ + dd] = o;
    }
}

// ---------------------------------------------------------------------------
// Reduce-scatter over 32 lanes: input acc[8] packed u64 = 16 floats (d pairs).
// Returns full 32-lane sum for d = f(lane); every xor-1 lane pair agrees.
// ---------------------------------------------------------------------------
__device__ __forceinline__ float reduce16(const u64 acc[8], int lane, int& dOut)
{
    bool k16 = (lane & 16) == 0;
    u64 h[4];
    #pragma unroll
    for (int j = 0; j < 4; j++) {
        u64 send = k16 ? acc[4 + j] : acc[j];
        u64 recv = __shfl_xor_sync(0xffffffffu, send, 16);
        u64 mine = k16 ? acc[j] : acc[4 + j];
        h[j] = add2_(mine, recv);
    }
    bool k8 = (lane & 8) == 0;
    u64 g[2];
    #pragma unroll
    for (int j = 0; j < 2; j++) {
        u64 send = k8 ? h[2 + j] : h[j];
        u64 recv = __shfl_xor_sync(0xffffffffu, send, 8);
        u64 mine = k8 ? h[j] : h[2 + j];
        g[j] = add2_(mine, recv);
    }
    bool k4 = (lane & 4) == 0;
    {
        u64 send = k4 ? g[1] : g[0];
        u64 recv = __shfl_xor_sync(0xffffffffu, send, 4);
        u64 mine = k4 ? g[0] : g[1];
        g[0] = add2_(mine, recv);
    }
    float lo, hi; upk(g[0], lo, hi);
    bool k2 = (lane & 2) == 0;
    float send = k2 ? hi : lo;
    float recv = __shfl_xor_sync(0xffffffffu, send, 2);
    float s = (k2 ? lo : hi) + recv;
    s += __shfl_xor_sync(0xffffffffu, s, 1);
    dOut = ((lane & 16) >> 1) | ((lane & 8) >> 1) | ((lane & 4) >> 1) | ((lane & 2) >> 1);
    return s;
}

// ---------------------------------------------------------------------------
// Kernel B: fused scores + mixing-MLP + softmax + AV.
// One warp per TWO rows.  MLP identity:
//   sum_m w2*relu(t_m) = A*dot + B*cost + [C] + sum_m (0.5*w2_m)*|t_m|
// with A = sum 0.5*w2*w1a, B = sum 0.5*w2*w1b; C and mix2_bias are
// softmax-invariant (dropped).  1/sqrt(D) folded into w1a.
// (256,3): regs ~80 (no spills), 3 blocks/SM.
// ---------------------------------------------------------------------------
__global__ __launch_bounds__(256, 3) void attn_kernel(
    const float* __restrict__ cost_mat,
    const float* __restrict__ mix1_w,   // [16][2][32]
    const float* __restrict__ mix1_b,   // [16][32]
    const float* __restrict__ mix2_w,   // [16][32][1]
    float* __restrict__ out)            // [B][R][H*D]
{
    __shared__ __align__(16) float Ks[256][20];
    __shared__ __align__(16) float Vs[256][20];
    __shared__ u64   mlpp[32][4];       // (wx pair, wy pair, b1 pair, 0.5*w2 pair)
    __shared__ u64   ABs[2];            // packed (A,A), (B,B)

    int b = blockIdx.z, h = blockIdx.y, rt = blockIdx.x;
    int bh = b * H_ + h;
    int t = threadIdx.x;
    int lane = t & 31, w = t >> 5;
    int r0 = rt * 16 + w * 2;           // this warp handles rows r0, r0+1

    // ---- cooperative K/V tile staging ----
    {
        const float* Kg = g_K + bh * NQ * D_;
        const float* Vg = g_V + bh * NQ * D_;
        #pragma unroll
        for (int j = 0; j < 4; j++) {
            *(float4*)&Ks[t][j * 4] = *(const float4*)&Kg[t * D_ + j * 4];
            *(float4*)&Vs[t][j * 4] = *(const float4*)&Vg[t * D_ + j * 4];
        }
    }
    if (t < 32) {
        float wxv = mix1_w[h * 64 + t] * 0.25f;   // fold 1/sqrt(D)
        float wyv = mix1_w[h * 64 + 32 + t];
        float bzv = mix1_b[h * 32 + t];
        float hwv = mix2_w[h * 32 + t] * 0.5f;    // fold 0.5 of abs-relu identity
        mlpp[t][0] = pk(wxv, wxv);
        mlpp[t][1] = pk(wyv, wyv);
        mlpp[t][2] = pk(bzv, bzv);
        mlpp[t][3] = pk(hwv, hwv);
        float a  = hwv * wxv;
        float bb = hwv * wyv;
        #pragma unroll
        for (int o = 16; o; o >>= 1) {
            a  += __shfl_xor_sync(0xffffffffu, a, o);
            bb += __shfl_xor_sync(0xffffffffu, bb, o);
        }
        if (t == 0) { ABs[0] = pk(a, a); ABs[1] = pk(bb, bb); }
    }
    __syncthreads();

    // ---- Phase 1: raw dot scores (scale folded into wx) ----
    float q0[16], q1[16];
    {
        const float* Qg = g_Q + (bh * NQ + r0) * D_;
        #pragma unroll
        for (int j = 0; j < 4; j++) {
            float4 a = *(const float4*)&Qg[j * 4];
            float4 c = *(const float4*)&Qg[16 + j * 4];
            q0[j*4+0] = a.x; q0[j*4+1] = a.y; q0[j*4+2] = a.z; q0[j*4+3] = a.w;
            q1[j*4+0] = c.x; q1[j*4+1] = c.y; q1[j*4+2] = c.z; q1[j*4+3] = c.w;
        }
    }
    u64 dp0[4], dp1[4];
    #pragma unroll
    for (int p = 0; p < 4; p++) {
        int ca = (2 * p) * 32 + lane;
        int cb = ca + 32;
        float sa0 = 0.f, sa1 = 0.f, sb0 = 0.f, sb1 = 0.f;
        #pragma unroll
        for (int j = 0; j < 4; j++) {
            float4 ka = *(const float4*)&Ks[ca][j * 4];
            float4 kb = *(const float4*)&Ks[cb][j * 4];
            sa0 = fmaf(q0[j*4+0], ka.x, sa0); sa0 = fmaf(q0[j*4+1], ka.y, sa0);
            sa0 = fmaf(q0[j*4+2], ka.z, sa0); sa0 = fmaf(q0[j*4+3], ka.w, sa0);
            sa1 = fmaf(q1[j*4+0], ka.x, sa1); sa1 = fmaf(q1[j*4+1], ka.y, sa1);
            sa1 = fmaf(q1[j*4+2], ka.z, sa1); sa1 = fmaf(q1[j*4+3], ka.w, sa1);
            sb0 = fmaf(q0[j*4+0], kb.x, sb0); sb0 = fmaf(q0[j*4+1], kb.y, sb0);
            sb0 = fmaf(q0[j*4+2], kb.z, sb0); sb0 = fmaf(q0[j*4+3], kb.w, sb0);
            sb1 = fmaf(q1[j*4+0], kb.x, sb1); sb1 = fmaf(q1[j*4+1], kb.y, sb1);
            sb1 = fmaf(q1[j*4+2], kb.z, sb1); sb1 = fmaf(q1[j*4+3], kb.w, sb1);
        }
        dp0[p] = pk(sa0, sb0);
        dp1[p] = pk(sa1, sb1);
    }

    // ---- cost loads (after phase 1 so q regs can retire first) ----
    const float* cr0 = cost_mat + (b * NQ + r0) * NQ;
    const float* cr1 = cr0 + NQ;
    u64 cp0[4], cp1[4];
    #pragma unroll
    for (int p = 0; p < 4; p++) {
        int ca = (2 * p) * 32 + lane;
        cp0[p] = pk(__ldg(cr0 + ca), __ldg(cr0 + ca + 32));
        cp1[p] = pk(__ldg(cr1 + ca), __ldg(cr1 + ca + 32));
    }

    // ---- Phase 2: mixing MLP (abs half only; linear half analytic) ----
    u64 A2 = ABs[0], B2 = ABs[1];
    u64 s0[4], s1[4];
    #pragma unroll
    for (int p = 0; p < 4; p++) {
        s0[p] = fma2_(B2, cp0[p], mul2_(A2, dp0[p]));
        s1[p] = fma2_(B2, cp1[p], mul2_(A2, dp1[p]));
    }
    #pragma unroll 4
    for (int m = 0; m < 32; m++) {
        ulonglong2 w01 = *(const ulonglong2*)&mlpp[m][0];
        ulonglong2 w23 = *(const ulonglong2*)&mlpp[m][2];
        u64 wxx = w01.x, wyy = w01.y, wzz = w23.x, hww = w23.y;
        #pragma unroll
        for (int p = 0; p < 4; p++) {
            u64 t0 = fma2_(wxx, dp0[p], fma2_(wyy, cp0[p], wzz));
            s0[p] = fma2_(hww, t0 & ABSM, s0[p]);
            u64 t1 = fma2_(wxx, dp1[p], fma2_(wyy, cp1[p], wzz));
            s1[p] = fma2_(hww, t1 & ABSM, s1[p]);
        }
    }

    // ---- Phase 3: softmax per row ----
    float sc0[8], sc1[8];
    #pragma unroll
    for (int p = 0; p < 4; p++) {
        upk(s0[p], sc0[2 * p], sc0[2 * p + 1]);
        upk(s1[p], sc1[2 * p], sc1[2 * p + 1]);
    }
    float mx0 = sc0[0], mx1 = sc1[0];
    #pragma unroll
    for (int i = 1; i < 8; i++) { mx0 = fmaxf(mx0, sc0[i]); mx1 = fmaxf(mx1, sc1[i]); }
    #pragma unroll
    for (int o = 16; o; o >>= 1) {
        mx0 = fmaxf(mx0, __shfl_xor_sync(0xffffffffu, mx0, o));
        mx1 = fmaxf(mx1, __shfl_xor_sync(0xffffffffu, mx1, o));
    }
    float sum0 = 0.f, sum1 = 0.f;
    #pragma unroll
    for (int i = 0; i < 8; i++) {
        sc0[i] = __expf(sc0[i] - mx0); sum0 += sc0[i];
        sc1[i] = __expf(sc1[i] - mx1); sum1 += sc1[i];
    }
    #pragma unroll
    for (int o = 16; o; o >>= 1) {
        sum0 += __shfl_xor_sync(0xffffffffu, sum0, o);
        sum1 += __shfl_xor_sync(0xffffffffu, sum1, o);
    }
    float inv0 = 1.f / sum0, inv1 = 1.f / sum1;

    // ---- Phase 4: AV accumulation (packed over d pairs; V pairs are free
    //      ulonglong2 views of the 16B-aligned smem rows) ----
    u64 acc0[8], acc1[8];
    #pragma unroll
    for (int j = 0; j < 8; j++) { acc0[j] = 0ull; acc1[j] = 0ull; }
    #pragma unroll
    for (int i = 0; i < 8; i++) {
        int c = i * 32 + lane;
        u64 w0 = pk(sc0[i], sc0[i]);
        u64 w1 = pk(sc1[i], sc1[i]);
        #pragma unroll
        for (int j = 0; j < 4; j++) {
            ulonglong2 vv = *(const ulonglong2*)&Vs[c][j * 4];
            acc0[2 * j]     = fma2_(w0, vv.x, acc0[2 * j]);
            acc0[2 * j + 1] = fma2_(w0, vv.y, acc0[2 * j + 1]);
            acc1[2 * j]     = fma2_(w1, vv.x, acc1[2 * j]);
            acc1[2 * j + 1] = fma2_(w1, vv.y, acc1[2 * j + 1]);
        }
    }

    // ---- Phase 5: reduce-scatter epilogue ----
    int d0;
    float res0 = reduce16(acc0, lane, d0);
    int d1;
    float res1 = reduce16(acc1, lane, d1);
    if ((lane & 1) == 0) {
        out[(b * NQ + r0)     * (H_ * D_) + h * D_ + d0] = res0 * inv0;
        out[(b * NQ + r0 + 1) * (H_ * D_) + h * D_ + d1] = res1 * inv1;
    }
}

extern "C" void kernel_launch(void* const* d_in, const int* in_sizes, int n_in,
                              void* d_out, int out_size)
{
    const float* row_emb  = (const float*)d_in[0];
    const float* col_emb  = (const float*)d_in[1];
    const float* cost_mat = (const float*)d_in[2];
    const float* Wq       = (const float*)d_in[3];
    const float* Wk       = (const float*)d_in[4];
    const float* Wv       = (const float*)d_in[5];
    const float* m1w      = (const float*)d_in[6];
    const float* m1b      = (const float*)d_in[7];
    const float* m2w      = (const float*)d_in[8];
    // d_in[9] = mix2_bias: softmax-invariant, intentionally unused.
    float* out = (float*)d_out;

    dim3 gA(4, 32, 3);   // n-tiles x m-tiles x {Q,K,V} = 384 blocks
    qkv_kernel<<<gA, 128>>>(row_emb, col_emb, Wq, Wk, Wv);

    dim3 gB(16, 16, 4);  // 16-row tiles x heads x batch
    attn_kernel<<<gB, 256>>>(cost_mat, m1w, m1b, m2w, out);
}